// round 5
// baseline (speedup 1.0000x reference)
#include <cuda_runtime.h>
#include <cuda_bf16.h>
#include <stdint.h>

// out[token, :] = sign(weight[id, :]) * max(scales[id, col/128], 1e-8)
// ids: int32 [16384], weight: f32 [50257,1024], scales: f32 [50257,8]
//
// Persistent grid-stride version of the MLP-8 register kernel:
//  - grid sized to ~2 blocks/SM resident, each block loops over token chunks
//    (no 111-wave block churn, no ragged tail)
//  - weight loads via __ldcg (L2-only; weight lines are never L1-reused)
//  - output via __stcs streaming stores (never re-read)
//  - 8 independent float4 weight loads in flight per thread (MLP ~8)

#define DIM     1024
#define NGROUP  8
#define THREADS 256
#define TPB     8      // tokens per chunk
#define NSM     148
#define BLOCKS  (NSM * 8)   // resident-sized persistent grid

__global__ __launch_bounds__(THREADS)
void literati_embed_kernel(const int* __restrict__ ids,
                           const float* __restrict__ weight,
                           const float* __restrict__ scales,
                           float* __restrict__ out,
                           int n_tokens)
{
    const int t   = threadIdx.x;
    const int col = t * 4;
    const int g   = t >> 5;   // scale group, warp-uniform

    const int n_chunks = (n_tokens + TPB - 1) / TPB;

    for (int chunk = blockIdx.x; chunk < n_chunks; chunk += gridDim.x) {
        const int tok0 = chunk * TPB;

        int rows[TPB];
#pragma unroll
        for (int i = 0; i < TPB; i++) {
            int tok = tok0 + i;
            rows[i] = (tok < n_tokens) ? __ldg(&ids[tok]) : 0;
        }

        float s[TPB];
#pragma unroll
        for (int i = 0; i < TPB; i++)
            s[i] = __ldg(&scales[(size_t)rows[i] * NGROUP + g]);

        // Front-batched independent weight loads, L2-only
        float4 w[TPB];
#pragma unroll
        for (int i = 0; i < TPB; i++)
            w[i] = __ldcg(reinterpret_cast<const float4*>(
                &weight[(size_t)rows[i] * DIM + col]));

#pragma unroll
        for (int i = 0; i < TPB; i++) {
            float sc = fmaxf(s[i], 1e-8f);
            float4 o;
            o.x = (w[i].x < 0.0f) ? -sc : sc;
            o.y = (w[i].y < 0.0f) ? -sc : sc;
            o.z = (w[i].z < 0.0f) ? -sc : sc;
            o.w = (w[i].w < 0.0f) ? -sc : sc;
            int tok = tok0 + i;
            if (tok < n_tokens)
                __stcs(reinterpret_cast<float4*>(&out[(size_t)tok * DIM + col]), o);
        }
    }
}

extern "C" void kernel_launch(void* const* d_in, const int* in_sizes, int n_in,
                              void* d_out, int out_size)
{
    const int* ids      = (const int*)d_in[0];
    const float* weight = (const float*)d_in[1];
    const float* scales = (const float*)d_in[2];
    float* out          = (float*)d_out;

    const int n_tokens = in_sizes[0];  // 16384

    int blocks = BLOCKS;
    int n_chunks = (n_tokens + TPB - 1) / TPB;
    if (blocks > n_chunks) blocks = n_chunks;

    literati_embed_kernel<<<blocks, THREADS>>>(ids, weight, scales, out, n_tokens);
}